// round 13
// baseline (speedup 1.0000x reference)
#include <cuda_runtime.h>
#include <cstdint>

// ---------------------------------------------------------------------------
// Fused SSIM(11x11 gaussian) + Charbonnier + MSE — sum/diff + packed f32x2.
// R7 structure (32x32 tile, 256 thr, static smem, FFMA2 + LDS.64/STS.64,
// bank-conflict-free strides) with ONE change: vertical blocking RG=4 so
// phase 3 runs 256 tasks on all 8 warps (was 128 tasks on 4 warps),
// halving the per-thread dependency chain and freeing idle issue slots.
// ---------------------------------------------------------------------------

#define WIN   11
#define RAD   5
#define TX    32
#define TY    32
#define HX    42
#define HY    42
#define SR2   43            // raw row stride in ull units
#define SH2   33            // intermediate row stride in ull units
#define IMG_H 512
#define IMG_W 512
#define NTHREADS 256
#define CG    8             // cols per horizontal task: 42*4 = 168 tasks
#define RG    4             // rows per vertical thread: 32*8 = 256 tasks

typedef unsigned long long ull;

__device__ __forceinline__ ull pk(float a, float b) {
    return ((ull)__float_as_uint(b) << 32) | (ull)__float_as_uint(a);
}
__device__ __forceinline__ float flo(ull v) { return __uint_as_float((unsigned)v); }
__device__ __forceinline__ float fhi(ull v) { return __uint_as_float((unsigned)(v >> 32)); }

__device__ __forceinline__ ull fma2(ull a, ull b, ull c) {
    ull d;
    asm("fma.rn.f32x2 %0, %1, %2, %3;" : "=l"(d) : "l"(a), "l"(b), "l"(c));
    return d;
}
__device__ __forceinline__ ull mul2(ull a, ull b) {
    ull d;
    asm("mul.rn.f32x2 %0, %1, %2;" : "=l"(d) : "l"(a), "l"(b));
    return d;
}
__device__ __forceinline__ float sqrt_approx(float x) {
    float r;
    asm("sqrt.approx.f32 %0, %1;" : "=f"(r) : "f"(x));
    return r;
}

__device__ __forceinline__ float cw(int i) {
    constexpr float W[WIN] = {
        0.00102838f, 0.00759876f, 0.03600077f, 0.10936069f, 0.21300553f,
        0.26601172f,
        0.21300553f, 0.10936069f, 0.03600077f, 0.00759876f, 0.00102838f };
    return W[i];
}

__global__ __launch_bounds__(NTHREADS)
void ssim_charb_mse_kernel(const float* __restrict__ pred,
                           const float* __restrict__ targ,
                           float* __restrict__ out)
{
    __shared__ ull s_raw[HY * SR2];   // 14448 B : packed (s, d)
    __shared__ ull h_a[HY * SH2];     // 11088 B : packed (G_h s,   G_h d)
    __shared__ ull h_b[HY * SH2];     // 11088 B : packed (G_h s^2, G_h d^2)

    const int plane = blockIdx.z;
    const int x0 = blockIdx.x * TX;
    const int y0 = blockIdx.y * TY;
    const size_t pbase = (size_t)plane * IMG_H * IMG_W;
    const float* __restrict__ p = pred + pbase;
    const float* __restrict__ t = targ + pbase;
    float* __restrict__ o = out + pbase;

    const int tid = threadIdx.x;

    // ---- 1. halo load: pack (s,d); interior CTAs skip bounds checks ----
    const bool interior = (x0 >= RAD) & (x0 + TX + RAD <= IMG_W) &
                          (y0 >= RAD) & (y0 + TY + RAD <= IMG_H);
    if (interior) {
        const int gb = (y0 - RAD) * IMG_W + (x0 - RAD);
        #pragma unroll 1
        for (int idx = tid; idx < HY * HX; idx += NTHREADS) {
            const int r = idx / HX;
            const int c = idx - r * HX;
            const int g = gb + r * IMG_W + c;
            const float pv = p[g];
            const float tv = t[g];
            s_raw[r * SR2 + c] = pk(pv + tv, pv - tv);
        }
    } else {
        #pragma unroll 1
        for (int idx = tid; idx < HY * HX; idx += NTHREADS) {
            const int r = idx / HX;
            const int c = idx - r * HX;
            const int gy = y0 + r - RAD;
            const int gx = x0 + c - RAD;
            float sv = 0.f, dv = 0.f;
            if ((unsigned)gy < (unsigned)IMG_H && (unsigned)gx < (unsigned)IMG_W) {
                const int g = gy * IMG_W + gx;
                const float pv = p[g];
                const float tv = t[g];
                sv = pv + tv;
                dv = pv - tv;
            }
            s_raw[r * SR2 + c] = pk(sv, dv);
        }
    }
    __syncthreads();

    // ---- 2. horizontal pass: 168 tasks (42 rows x 4 col-groups), CG=8 ----
    if (tid < HY * (TX / CG)) {                // 168 < 256: one round
        const int g  = tid / HY;               // col group 0..3
        const int r  = tid - g * HY;           // row 0..41 (consecutive per lane)
        const int c0 = g * CG;
        const int rb = r * SR2 + c0;

        ull m1[CG], m2[CG];
        #pragma unroll
        for (int k = 0; k < CG; ++k) { m1[k] = 0ULL; m2[k] = 0ULL; }

        #pragma unroll
        for (int i = 0; i < CG + WIN - 1; ++i) {          // 18 inputs
            const ull v  = s_raw[rb + i];                 // (s, d)
            const ull v2 = mul2(v, v);                    // (s^2, d^2)
            #pragma unroll
            for (int k = 0; k < CG; ++k) {
                const int tap = i - k;
                if (tap >= 0 && tap < WIN) {
                    const ull w = pk(cw(tap), cw(tap));
                    m1[k] = fma2(w, v,  m1[k]);
                    m2[k] = fma2(w, v2, m2[k]);
                }
            }
        }
        const int hb = r * SH2 + c0;
        #pragma unroll
        for (int k = 0; k < CG; ++k) {
            h_a[hb + k] = m1[k];
            h_b[hb + k] = m2[k];
        }
    }
    __syncthreads();

    // ---- 3. vertical pass + loss: 256 tasks (all 8 warps), RG=4 strips ----
    {
        const int c     = tid & 31;
        const int strip = tid >> 5;            // 0..7
        const int r0    = strip * RG;

        ull E1[RG], E2[RG];
        #pragma unroll
        for (int k = 0; k < RG; ++k) { E1[k] = 0ULL; E2[k] = 0ULL; }

        #pragma unroll
        for (int j = 0; j < RG + WIN - 1; ++j) {          // 14 h-rows
            const int hb = (r0 + j) * SH2 + c;
            const ull va = h_a[hb];
            const ull vb = h_b[hb];
            #pragma unroll
            for (int k = 0; k < RG; ++k) {
                const int tap = j - k;
                if (tap >= 0 && tap < WIN) {
                    const ull w = pk(cw(tap), cw(tap));
                    E1[k] = fma2(w, va, E1[k]);
                    E2[k] = fma2(w, vb, E2[k]);
                }
            }
        }

        const float C1 = 0.0001f;       // (0.01)^2
        const float C2 = 0.0009f;       // (0.03)^2
        const float EPS2 = 1e-12f;      // (1e-6)^2

        #pragma unroll
        for (int k = 0; k < RG; ++k) {
            const float Es  = flo(E1[k]), Ed  = fhi(E1[k]);
            const float Es2 = flo(E2[k]), Ed2 = fhi(E2[k]);

            const float mus2 = Es * Es;              // (mx+my)^2
            const float mud2 = Ed * Ed;              // (mx-my)^2
            const float dif  = 0.5f * (mus2 - mud2); // 2 mx my
            const float sum  = 0.5f * (mus2 + mud2); // mx^2 + my^2

            const float A1 = dif + C1;
            const float B1 = sum + C1;
            const float A2 = 0.5f * (Es2 - Ed2) - dif + C2;
            const float B2 = 0.5f * (Es2 + Ed2) - sum + C2;
            const float ssim = __fdividef(A1 * A2, B1 * B2);

            const float dcen = fhi(s_raw[(r0 + k + RAD) * SR2 + (c + RAD)]);
            const float d2c  = dcen * dcen;
            const float charb = sqrt_approx(d2c + EPS2);
            const float loss = 0.3f * charb + 2.0f * d2c + 0.6f * (1.f - ssim);

            o[(y0 + r0 + k) * IMG_W + (x0 + c)] = loss;
        }
    }
}

extern "C" void kernel_launch(void* const* d_in, const int* in_sizes, int n_in,
                              void* d_out, int out_size)
{
    const float* pred = (const float*)d_in[0];
    const float* targ = (const float*)d_in[1];
    float* out = (float*)d_out;

    const int planes = out_size / (IMG_H * IMG_W);   // 48
    dim3 grid(IMG_W / TX, IMG_H / TY, planes);       // 16,16,48
    dim3 block(NTHREADS);
    ssim_charb_mse_kernel<<<grid, block>>>(pred, targ, out);
}

// round 14
// speedup vs baseline: 1.0033x; 1.0033x over previous
#include <cuda_runtime.h>
#include <cstdint>

// ---------------------------------------------------------------------------
// Fused SSIM(11x11 gaussian) + Charbonnier + MSE — sum/diff + packed f32x2.
// R7 structure exactly (32x32 tile, 256 thr, static smem, conflict-free
// strides, FFMA2/LDS.64, RG=8 vertical) with ONE change: the horizontal pass
// uses symmetric-tap folding (w[i]==w[10-i]):
//     acc = w5*v[c+5]            (MUL2, rt2)
//     acc += w_i*(v[c+i]+v[c+10-i])  i=0..4   (ADD2 rt2 + FFMA2 rt3)
// 27 fma-pipe cyc per output vs 33 for 11 straight FFMA2 (rt=3 from register
// banking), same instruction count. Window of 18 inputs held in registers.
// ---------------------------------------------------------------------------

#define WIN   11
#define RAD   5
#define TX    32
#define TY    32
#define HX    42
#define HY    42
#define SR2   43            // raw row stride in ull units
#define SH2   33            // intermediate row stride in ull units
#define IMG_H 512
#define IMG_W 512
#define NTHREADS 256
#define CG    8             // cols per horizontal task: 42*4 = 168 tasks
#define RG    8             // rows per vertical thread: 32*4 = 128 tasks

typedef unsigned long long ull;

__device__ __forceinline__ ull pk(float a, float b) {
    return ((ull)__float_as_uint(b) << 32) | (ull)__float_as_uint(a);
}
__device__ __forceinline__ float flo(ull v) { return __uint_as_float((unsigned)v); }
__device__ __forceinline__ float fhi(ull v) { return __uint_as_float((unsigned)(v >> 32)); }

__device__ __forceinline__ ull fma2(ull a, ull b, ull c) {
    ull d;
    asm("fma.rn.f32x2 %0, %1, %2, %3;" : "=l"(d) : "l"(a), "l"(b), "l"(c));
    return d;
}
__device__ __forceinline__ ull mul2(ull a, ull b) {
    ull d;
    asm("mul.rn.f32x2 %0, %1, %2;" : "=l"(d) : "l"(a), "l"(b));
    return d;
}
__device__ __forceinline__ ull add2(ull a, ull b) {
    ull d;
    asm("add.rn.f32x2 %0, %1, %2;" : "=l"(d) : "l"(a), "l"(b));
    return d;
}
__device__ __forceinline__ float sqrt_approx(float x) {
    float r;
    asm("sqrt.approx.f32 %0, %1;" : "=f"(r) : "f"(x));
    return r;
}

__device__ __forceinline__ float cw(int i) {
    constexpr float W[WIN] = {
        0.00102838f, 0.00759876f, 0.03600077f, 0.10936069f, 0.21300553f,
        0.26601172f,
        0.21300553f, 0.10936069f, 0.03600077f, 0.00759876f, 0.00102838f };
    return W[i];
}

__global__ __launch_bounds__(NTHREADS, 4)
void ssim_charb_mse_kernel(const float* __restrict__ pred,
                           const float* __restrict__ targ,
                           float* __restrict__ out)
{
    __shared__ ull s_raw[HY * SR2];   // 14448 B : packed (s, d)
    __shared__ ull h_a[HY * SH2];     // 11088 B : packed (G_h s,   G_h d)
    __shared__ ull h_b[HY * SH2];     // 11088 B : packed (G_h s^2, G_h d^2)

    const int plane = blockIdx.z;
    const int x0 = blockIdx.x * TX;
    const int y0 = blockIdx.y * TY;
    const size_t pbase = (size_t)plane * IMG_H * IMG_W;
    const float* __restrict__ p = pred + pbase;
    const float* __restrict__ t = targ + pbase;
    float* __restrict__ o = out + pbase;

    const int tid = threadIdx.x;

    // ---- 1. halo load: pack (s,d); interior CTAs skip bounds checks ----
    const bool interior = (x0 >= RAD) & (x0 + TX + RAD <= IMG_W) &
                          (y0 >= RAD) & (y0 + TY + RAD <= IMG_H);
    if (interior) {
        const int gb = (y0 - RAD) * IMG_W + (x0 - RAD);
        #pragma unroll 1
        for (int idx = tid; idx < HY * HX; idx += NTHREADS) {
            const int r = idx / HX;
            const int c = idx - r * HX;
            const int g = gb + r * IMG_W + c;
            const float pv = p[g];
            const float tv = t[g];
            s_raw[r * SR2 + c] = pk(pv + tv, pv - tv);
        }
    } else {
        #pragma unroll 1
        for (int idx = tid; idx < HY * HX; idx += NTHREADS) {
            const int r = idx / HX;
            const int c = idx - r * HX;
            const int gy = y0 + r - RAD;
            const int gx = x0 + c - RAD;
            float sv = 0.f, dv = 0.f;
            if ((unsigned)gy < (unsigned)IMG_H && (unsigned)gx < (unsigned)IMG_W) {
                const int g = gy * IMG_W + gx;
                const float pv = p[g];
                const float tv = t[g];
                sv = pv + tv;
                dv = pv - tv;
            }
            s_raw[r * SR2 + c] = pk(sv, dv);
        }
    }
    __syncthreads();

    // ---- 2. horizontal pass: 168 tasks, symmetric-folded, window in regs ----
    if (tid < HY * (TX / CG)) {                // 168 < 256: one round
        const int g  = tid / HY;               // col group 0..3
        const int r  = tid - g * HY;           // row 0..41 (consecutive per lane)
        const int c0 = g * CG;
        const int rb = r * SR2 + c0;
        const int hb = r * SH2 + c0;

        ull v[CG + WIN - 1];                   // 18-column window
        #pragma unroll
        for (int i = 0; i < CG + WIN - 1; ++i)
            v[i] = s_raw[rb + i];

        // chan A: (G_h s, G_h d); store per output to keep liveness low
        #pragma unroll
        for (int k = 0; k < CG; ++k) {
            ull acc = mul2(pk(cw(5), cw(5)), v[k + 5]);
            #pragma unroll
            for (int i = 0; i < 5; ++i) {
                const ull s2 = add2(v[k + i], v[k + 10 - i]);
                acc = fma2(pk(cw(i), cw(i)), s2, acc);
            }
            h_a[hb + k] = acc;
        }

        // square the window in place, then chan B: (G_h s^2, G_h d^2)
        #pragma unroll
        for (int i = 0; i < CG + WIN - 1; ++i)
            v[i] = mul2(v[i], v[i]);

        #pragma unroll
        for (int k = 0; k < CG; ++k) {
            ull acc = mul2(pk(cw(5), cw(5)), v[k + 5]);
            #pragma unroll
            for (int i = 0; i < 5; ++i) {
                const ull s2 = add2(v[k + i], v[k + 10 - i]);
                acc = fma2(pk(cw(i), cw(i)), s2, acc);
            }
            h_b[hb + k] = acc;
        }
    }
    __syncthreads();

    // ---- 3. vertical pass + loss: 128 tasks, 8-row strips (R7 exact) ----
    if (tid < TX * (TY / RG)) {                // 128 < 256: one round
        const int c    = tid & 31;
        const int strip= tid >> 5;             // 0..3
        const int r0   = strip * RG;

        ull E1[RG], E2[RG];
        #pragma unroll
        for (int k = 0; k < RG; ++k) { E1[k] = 0ULL; E2[k] = 0ULL; }

        #pragma unroll
        for (int j = 0; j < RG + WIN - 1; ++j) {          // 18 h-rows
            const int hb = (r0 + j) * SH2 + c;
            const ull va = h_a[hb];
            const ull vb = h_b[hb];
            #pragma unroll
            for (int k = 0; k < RG; ++k) {
                const int tap = j - k;
                if (tap >= 0 && tap < WIN) {
                    const ull w = pk(cw(tap), cw(tap));
                    E1[k] = fma2(w, va, E1[k]);
                    E2[k] = fma2(w, vb, E2[k]);
                }
            }
        }

        const float C1 = 0.0001f;       // (0.01)^2
        const float C2 = 0.0009f;       // (0.03)^2
        const float EPS2 = 1e-12f;      // (1e-6)^2

        #pragma unroll
        for (int k = 0; k < RG; ++k) {
            const float Es  = flo(E1[k]), Ed  = fhi(E1[k]);
            const float Es2 = flo(E2[k]), Ed2 = fhi(E2[k]);

            const float mus2 = Es * Es;              // (mx+my)^2
            const float mud2 = Ed * Ed;              // (mx-my)^2
            const float dif  = 0.5f * (mus2 - mud2); // 2 mx my
            const float sum  = 0.5f * (mus2 + mud2); // mx^2 + my^2

            const float A1 = dif + C1;
            const float B1 = sum + C1;
            const float A2 = 0.5f * (Es2 - Ed2) - dif + C2;
            const float B2 = 0.5f * (Es2 + Ed2) - sum + C2;
            const float ssim = __fdividef(A1 * A2, B1 * B2);

            const float dcen = fhi(s_raw[(r0 + k + RAD) * SR2 + (c + RAD)]);
            const float d2c  = dcen * dcen;
            const float charb = sqrt_approx(d2c + EPS2);
            const float loss = 0.3f * charb + 2.0f * d2c + 0.6f * (1.f - ssim);

            o[(y0 + r0 + k) * IMG_W + (x0 + c)] = loss;
        }
    }
}

extern "C" void kernel_launch(void* const* d_in, const int* in_sizes, int n_in,
                              void* d_out, int out_size)
{
    const float* pred = (const float*)d_in[0];
    const float* targ = (const float*)d_in[1];
    float* out = (float*)d_out;

    const int planes = out_size / (IMG_H * IMG_W);   // 48
    dim3 grid(IMG_W / TX, IMG_H / TY, planes);       // 16,16,48
    dim3 block(NTHREADS);
    ssim_charb_mse_kernel<<<grid, block>>>(pred, targ, out);
}

// round 15
// speedup vs baseline: 1.2447x; 1.2406x over previous
#include <cuda_runtime.h>
#include <cstdint>

// ---------------------------------------------------------------------------
// Fused SSIM(11x11 gaussian) + Charbonnier + MSE — sum/diff + packed f32x2.
// R7 champion structure byte-for-byte (32x32 tile, 256 thr, static smem,
// CG=8 / RG=8 input-stationary FFMA2 conv, LDS.64/STS.64, conflict-free
// strides) + ONE change: interior CTAs load the halo with float4 LDG.128
// (48-col aligned span, 1008 wide loads vs 3528 scalar LDG.32).
// ---------------------------------------------------------------------------

#define WIN   11
#define RAD   5
#define TX    32
#define TY    32
#define HX    42
#define HY    42
#define SR2   43            // raw row stride in ull units
#define SH2   33            // intermediate row stride in ull units
#define IMG_H 512
#define IMG_W 512
#define NTHREADS 256
#define CG    8             // cols per horizontal task: 42*4 = 168 tasks
#define RG    8             // rows per vertical thread: 32*4 = 128 tasks

typedef unsigned long long ull;

__device__ __forceinline__ ull pk(float a, float b) {
    return ((ull)__float_as_uint(b) << 32) | (ull)__float_as_uint(a);
}
__device__ __forceinline__ float flo(ull v) { return __uint_as_float((unsigned)v); }
__device__ __forceinline__ float fhi(ull v) { return __uint_as_float((unsigned)(v >> 32)); }

__device__ __forceinline__ ull fma2(ull a, ull b, ull c) {
    ull d;
    asm("fma.rn.f32x2 %0, %1, %2, %3;" : "=l"(d) : "l"(a), "l"(b), "l"(c));
    return d;
}
__device__ __forceinline__ ull mul2(ull a, ull b) {
    ull d;
    asm("mul.rn.f32x2 %0, %1, %2;" : "=l"(d) : "l"(a), "l"(b));
    return d;
}
__device__ __forceinline__ float sqrt_approx(float x) {
    float r;
    asm("sqrt.approx.f32 %0, %1;" : "=f"(r) : "f"(x));
    return r;
}

__device__ __forceinline__ float cw(int i) {
    constexpr float W[WIN] = {
        0.00102838f, 0.00759876f, 0.03600077f, 0.10936069f, 0.21300553f,
        0.26601172f,
        0.21300553f, 0.10936069f, 0.03600077f, 0.00759876f, 0.00102838f };
    return W[i];
}

__global__ __launch_bounds__(NTHREADS)
void ssim_charb_mse_kernel(const float* __restrict__ pred,
                           const float* __restrict__ targ,
                           float* __restrict__ out)
{
    __shared__ ull s_raw[HY * SR2];   // 14448 B : packed (s, d)
    __shared__ ull h_a[HY * SH2];     // 11088 B : packed (G_h s,   G_h d)
    __shared__ ull h_b[HY * SH2];     // 11088 B : packed (G_h s^2, G_h d^2)

    const int plane = blockIdx.z;
    const int x0 = blockIdx.x * TX;
    const int y0 = blockIdx.y * TY;
    const size_t pbase = (size_t)plane * IMG_H * IMG_W;
    const float* __restrict__ p = pred + pbase;
    const float* __restrict__ t = targ + pbase;
    float* __restrict__ o = out + pbase;

    const int tid = threadIdx.x;

    // ---- 1. halo load: pack (s,d); interior CTAs use float4 LDG.128 ----
    const bool interior = (x0 >= RAD) & (x0 + TX + RAD <= IMG_W) &
                          (y0 >= RAD) & (y0 + TY + RAD <= IMG_H);
    if (interior) {
        // aligned 48-col span [x0-8, x0+40): 12 float4 per row, 42 rows.
        // (x0-8)*4 bytes is 16B-aligned since x0 is a multiple of 32.
        const float* prow = p + (y0 - RAD) * IMG_W + (x0 - 8);
        const float* trow = t + (y0 - RAD) * IMG_W + (x0 - 8);
        #pragma unroll 1
        for (int v = tid; v < HY * 12; v += NTHREADS) {
            const int r = v / 12;
            const int j = v - r * 12;
            const float4 pv = *reinterpret_cast<const float4*>(prow + r * IMG_W + j * 4);
            const float4 tv = *reinterpret_cast<const float4*>(trow + r * IMG_W + j * 4);
            const float pa[4] = {pv.x, pv.y, pv.z, pv.w};
            const float ta[4] = {tv.x, tv.y, tv.z, tv.w};
            const int lc = j * 4 - 3;          // local col of component 0
            #pragma unroll
            for (int q = 0; q < 4; ++q) {
                const int c = lc + q;
                if ((unsigned)c < (unsigned)HX)
                    s_raw[r * SR2 + c] = pk(pa[q] + ta[q], pa[q] - ta[q]);
            }
        }
    } else {
        #pragma unroll 1
        for (int idx = tid; idx < HY * HX; idx += NTHREADS) {
            const int r = idx / HX;
            const int c = idx - r * HX;
            const int gy = y0 + r - RAD;
            const int gx = x0 + c - RAD;
            float sv = 0.f, dv = 0.f;
            if ((unsigned)gy < (unsigned)IMG_H && (unsigned)gx < (unsigned)IMG_W) {
                const int g = gy * IMG_W + gx;
                const float pv = p[g];
                const float tv = t[g];
                sv = pv + tv;
                dv = pv - tv;
            }
            s_raw[r * SR2 + c] = pk(sv, dv);
        }
    }
    __syncthreads();

    // ---- 2. horizontal pass: 168 tasks (42 rows x 4 col-groups), CG=8 ----
    if (tid < HY * (TX / CG)) {                // 168 < 256: one round
        const int g  = tid / HY;               // col group 0..3
        const int r  = tid - g * HY;           // row 0..41 (consecutive per lane)
        const int c0 = g * CG;
        const int rb = r * SR2 + c0;

        ull m1[CG], m2[CG];
        #pragma unroll
        for (int k = 0; k < CG; ++k) { m1[k] = 0ULL; m2[k] = 0ULL; }

        #pragma unroll
        for (int i = 0; i < CG + WIN - 1; ++i) {          // 18 inputs
            const ull v  = s_raw[rb + i];                 // (s, d)
            const ull v2 = mul2(v, v);                    // (s^2, d^2)
            #pragma unroll
            for (int k = 0; k < CG; ++k) {
                const int tap = i - k;
                if (tap >= 0 && tap < WIN) {
                    const ull w = pk(cw(tap), cw(tap));
                    m1[k] = fma2(w, v,  m1[k]);
                    m2[k] = fma2(w, v2, m2[k]);
                }
            }
        }
        const int hb = r * SH2 + c0;
        #pragma unroll
        for (int k = 0; k < CG; ++k) {
            h_a[hb + k] = m1[k];
            h_b[hb + k] = m2[k];
        }
    }
    __syncthreads();

    // ---- 3. vertical pass + loss: 128 tasks, 8-row column strips ----
    if (tid < TX * (TY / RG)) {                // 128 < 256: one round
        const int c    = tid & 31;
        const int strip= tid >> 5;             // 0..3
        const int r0   = strip * RG;

        ull E1[RG], E2[RG];
        #pragma unroll
        for (int k = 0; k < RG; ++k) { E1[k] = 0ULL; E2[k] = 0ULL; }

        #pragma unroll
        for (int j = 0; j < RG + WIN - 1; ++j) {          // 18 h-rows
            const int hb = (r0 + j) * SH2 + c;
            const ull va = h_a[hb];
            const ull vb = h_b[hb];
            #pragma unroll
            for (int k = 0; k < RG; ++k) {
                const int tap = j - k;
                if (tap >= 0 && tap < WIN) {
                    const ull w = pk(cw(tap), cw(tap));
                    E1[k] = fma2(w, va, E1[k]);
                    E2[k] = fma2(w, vb, E2[k]);
                }
            }
        }

        const float C1 = 0.0001f;       // (0.01)^2
        const float C2 = 0.0009f;       // (0.03)^2
        const float EPS2 = 1e-12f;      // (1e-6)^2

        #pragma unroll
        for (int k = 0; k < RG; ++k) {
            const float Es  = flo(E1[k]), Ed  = fhi(E1[k]);
            const float Es2 = flo(E2[k]), Ed2 = fhi(E2[k]);

            const float mus2 = Es * Es;              // (mx+my)^2
            const float mud2 = Ed * Ed;              // (mx-my)^2
            const float dif  = 0.5f * (mus2 - mud2); // 2 mx my
            const float sum  = 0.5f * (mus2 + mud2); // mx^2 + my^2

            const float A1 = dif + C1;
            const float B1 = sum + C1;
            const float A2 = 0.5f * (Es2 - Ed2) - dif + C2;
            const float B2 = 0.5f * (Es2 + Ed2) - sum + C2;
            const float ssim = __fdividef(A1 * A2, B1 * B2);

            const float dcen = fhi(s_raw[(r0 + k + RAD) * SR2 + (c + RAD)]);
            const float d2c  = dcen * dcen;
            const float charb = sqrt_approx(d2c + EPS2);
            const float loss = 0.3f * charb + 2.0f * d2c + 0.6f * (1.f - ssim);

            o[(y0 + r0 + k) * IMG_W + (x0 + c)] = loss;
        }
    }
}

extern "C" void kernel_launch(void* const* d_in, const int* in_sizes, int n_in,
                              void* d_out, int out_size)
{
    const float* pred = (const float*)d_in[0];
    const float* targ = (const float*)d_in[1];
    float* out = (float*)d_out;

    const int planes = out_size / (IMG_H * IMG_W);   // 48
    dim3 grid(IMG_W / TX, IMG_H / TY, planes);       // 16,16,48
    dim3 block(NTHREADS);
    ssim_charb_mse_kernel<<<grid, block>>>(pred, targ, out);
}